// round 2
// baseline (speedup 1.0000x reference)
#include <cuda_runtime.h>
#include <math.h>

#define Ntot 8192
#define KC   32
#define PC   64
#define FEATC 455          // 400 dist + 16 dmap + 15 dir + 15 vec + 9 rot
#define FSC   457          // padded feature stride (457 % 32 = 9, conflict-free)
#define THREADS 512

// ---- shared memory layout (float offsets) ----
#define OFF_WD    0                       // 455*64 = 29120
#define OFF_W1    29120                   // 64*128 = 8192
#define OFF_R     37312                   // reused region: features (32*457) OR pair/h/W2
#define OFF_PAIR  (OFF_R)                 // 32*65  = 2080
#define OFF_H     (OFF_R + 2080)          // 32*129 = 4128
#define OFF_W2    (OFF_R + 6208)          // 128*64 = 8192  (ends at OFF_R+14400 <= OFF_R+14624)
#define OFF_PJ    (OFF_R + 14624)         // 32*16 = 512   (= 51936)
#define OFF_POSN  (OFF_PJ + 512)          // 16            (= 52448)
#define OFF_RN    (OFF_POSN + 16)         // 9 R + 3 t     (= 52464)
#define OFF_SJ    (OFF_RN + 12)           // 32 ints
#define OFF_SREL  (OFF_SJ + 32)           // 32 ints
#define OFF_SSAME (OFF_SREL + 32)         // 32 floats
#define OFF_SPM   (OFF_SSAME + 32)        // 32 floats
#define SMEMF     (OFF_SPM + 32)          // 52604 floats = 210416 bytes

// ---------------- RBF: 16 bins with only 3 exps ----------------
// rbf_i = exp(-((d - c_i)/sigma)^2), c_i = i*22/15, sigma = 22/16.
// g = d/sigma, gamma = 16/15: rbf_i = exp(-(g - i*gamma)^2).
// Compute peak bin m exactly, then walk outward with geometric ratios.
// All ratios <= 1 starting from the rounded peak => no overflow; underflow to 0 is exact enough.
__device__ __forceinline__ void rbf16(float d, float* out) {
    const float SI = 0.72727272727f;   // 16/22
    const float G  = 1.06666666667f;   // 16/15
    const float Q  = 0.10273954f;      // exp(-2*G*G)
    float g = d * SI;
    int m = __float2int_rn(g * 0.9375f);   // g / G
    m = m < 0 ? 0 : (m > 15 ? 15 : m);
    float u = g - (float)m * G;
    float peak = __expf(-u * u);
    float r = __expf(G * (2.0f * u - G));   // ratio rbf_{m+1}/rbf_m
    float s = __expf(-G * (2.0f * u + G));  // ratio rbf_{m-1}/rbf_m
    out[m] = peak;
    float v = peak;
#pragma unroll
    for (int st = 1; st <= 15; ++st) {
        v *= r; r *= Q;
        int i = m + st;
        if (i <= 15) out[i] = v;
    }
    v = peak;
#pragma unroll
    for (int st = 1; st <= 15; ++st) {
        v *= s; s *= Q;
        int i = m - st;
        if (i >= 0) out[i] = v;
    }
}

// frames: p points at 9+ floats (atom rows 0..2 of one residue, xyz each)
__device__ __forceinline__ void frames_from(const float* p,
                                            float e1[3], float e2[3], float e3[3], float t[3]) {
    t[0] = p[3]; t[1] = p[4]; t[2] = p[5];
    float v1x = p[6] - t[0], v1y = p[7] - t[1], v1z = p[8] - t[2];
    float v2x = p[0] - t[0], v2y = p[1] - t[1], v2z = p[2] - t[2];
    float n1 = sqrtf(v1x * v1x + v1y * v1y + v1z * v1z) + 1e-6f;
    e1[0] = v1x / n1; e1[1] = v1y / n1; e1[2] = v1z / n1;
    float dt = v2x * e1[0] + v2y * e1[1] + v2z * e1[2];
    float ux = v2x - dt * e1[0], uy = v2y - dt * e1[1], uz = v2z - dt * e1[2];
    float n2 = sqrtf(ux * ux + uy * uy + uz * uz) + 1e-6f;
    e2[0] = ux / n2; e2[1] = uy / n2; e2[2] = uz / n2;
    e3[0] = e1[1] * e2[2] - e1[2] * e2[1];
    e3[1] = e1[2] * e2[0] - e1[0] * e2[2];
    e3[2] = e1[0] * e2[1] - e1[1] * e2[0];
}

__device__ __forceinline__ float gelu_f(float x) {
    float c = x + 0.044715f * x * x * x;
    return 0.5f * x * (1.0f + tanhf(0.7978845608028654f * c));
}

__global__ void __launch_bounds__(THREADS, 1)
dsd_kernel(const float* __restrict__ pos, const float* __restrict__ dmap,
           const int* __restrict__ nbrs, const int* __restrict__ resi,
           const int* __restrict__ chain, const int* __restrict__ batch,
           const float* __restrict__ maskp,
           const float* __restrict__ Wrel, const float* __restrict__ Wdmap,
           const float* __restrict__ Wdist, const float* __restrict__ Wdir,
           const float* __restrict__ Wrot, const float* __restrict__ Wvec,
           const float* __restrict__ lng, const float* __restrict__ lnb,
           const float* __restrict__ W1, const float* __restrict__ b1,
           const float* __restrict__ W2, const float* __restrict__ b2,
           float* __restrict__ outPair, float* __restrict__ outMask)
{
    extern __shared__ float sm[];
    const int tid = threadIdx.x;
    const int k = tid >> 4;       // neighbor slot 0..31
    const int sub = tid & 15;     // output sub-slice 0..15 (4 outputs each)

    // ---- stage constant weights once per block ----
    for (int i = tid; i < 400 * 64; i += THREADS) sm[OFF_WD + i] = Wdist[i];
    for (int i = tid; i < 16 * 64; i += THREADS) sm[OFF_WD + 400 * 64 + i] = Wdmap[i];
    for (int i = tid; i < 15 * 64; i += THREADS) sm[OFF_WD + 416 * 64 + i] = Wdir[i];
    for (int i = tid; i < 15 * 64; i += THREADS) sm[OFF_WD + 431 * 64 + i] = Wvec[i];
    for (int i = tid; i < 9 * 64; i += THREADS) sm[OFF_WD + 446 * 64 + i] = Wrot[i];
    for (int i = tid; i < 64 * 128; i += THREADS) sm[OFF_W1 + i] = W1[i];

    // per-thread constant params
    float lgr[4], lbr[4], b2r[4], b1r[8];
#pragma unroll
    for (int i = 0; i < 4; ++i) {
        lgr[i] = lng[sub * 4 + i];
        lbr[i] = lnb[sub * 4 + i];
        b2r[i] = b2[sub * 4 + i];
    }
#pragma unroll
    for (int i = 0; i < 8; ++i) b1r[i] = b1[sub * 8 + i];

    __syncthreads();

    int* smi = (int*)sm;

    for (int n = blockIdx.x; n < Ntot; n += gridDim.x) {
        // ---------- stage 1: neighbor meta, my pos, my frame ----------
        if (tid < 32) {
            int nb = nbrs[n * KC + tid];
            int j = nb < 0 ? 0 : nb;
            float valid = (nb != -1) ? 1.0f : 0.0f;
            smi[OFF_SJ + tid] = j;
            int dr = resi[j] - resi[n];
            dr = dr < -32 ? -32 : (dr > 32 ? 32 : dr);
            smi[OFF_SREL + tid] = dr + 32;
            float same = (chain[j] == chain[n] && batch[j] == batch[n]) ? 1.0f : 0.0f;
            sm[OFF_SSAME + tid] = same;
            float pm = maskp[n] * maskp[j] * valid;
            sm[OFF_SPM + tid] = pm;
            outMask[n * KC + tid] = pm;
        } else if (tid == 32) {
            float e1[3], e2[3], e3[3], t[3], prow[9];
#pragma unroll
            for (int i = 0; i < 9; ++i) prow[i] = pos[n * 15 + i];
            frames_from(prow, e1, e2, e3, t);
#pragma unroll
            for (int r = 0; r < 3; ++r) {
                sm[OFF_RN + r * 3 + 0] = e1[r];
                sm[OFF_RN + r * 3 + 1] = e2[r];
                sm[OFF_RN + r * 3 + 2] = e3[r];
            }
            sm[OFF_RN + 9 + 0] = t[0]; sm[OFF_RN + 9 + 1] = t[1]; sm[OFF_RN + 9 + 2] = t[2];
        } else if (tid >= 64 && tid < 79) {
            sm[OFF_POSN + tid - 64] = pos[n * 15 + (tid - 64)];
        }
        __syncthreads();

        // ---------- stage 2: gather neighbor positions ----------
        if (tid < 480) {
            int kk = tid / 15, e = tid - kk * 15;
            int j = smi[OFF_SJ + kk];
            sm[OFF_PJ + kk * 16 + e] = pos[j * 15 + e];
        }
        __syncthreads();

        // ---------- features ----------
        float* fk = sm + OFF_R + k * FSC;
        const float* pn = sm + OFF_POSN;
        const float* pj = sm + OFF_PJ + k * 16;
        {   // slot 1: distance pair dp = sub (0..15)
            int a = sub / 5, b = sub - a * 5;
            float dx = pn[a * 3 + 0] - pj[b * 3 + 0];
            float dy = pn[a * 3 + 1] - pj[b * 3 + 1];
            float dz = pn[a * 3 + 2] - pj[b * 3 + 2];
            float d = sqrtf(dx * dx + dy * dy + dz * dz);
            rbf16(d, fk + sub * 16);
        }
        if (sub < 9) {   // slot 2: distance pair dp = 16 + sub (16..24)
            int dp = 16 + sub;
            int a = dp / 5, b = dp - a * 5;
            float dx = pn[a * 3 + 0] - pj[b * 3 + 0];
            float dy = pn[a * 3 + 1] - pj[b * 3 + 1];
            float dz = pn[a * 3 + 2] - pj[b * 3 + 2];
            float d = sqrtf(dx * dx + dy * dy + dz * dz);
            rbf16(d, fk + dp * 16);
        } else if (sub == 9) {   // dmap rbf, masked
            int j = smi[OFF_SJ + k];
            float pm = sm[OFF_SPM + k];
            float dval = __ldg(&dmap[(long)n * Ntot + j]);
            if (pm > 0.0f) {
                rbf16(dval, fk + 400);
            } else {
#pragma unroll
                for (int i = 0; i < 16; ++i) fk[400 + i] = 0.0f;
            }
        } else if (sub < 15) {   // rel_vec + dirs for atom a = sub-10
            int a = sub - 10;
            float v0 = pj[a * 3 + 0] - sm[OFF_RN + 9 + 0];
            float v1 = pj[a * 3 + 1] - sm[OFF_RN + 9 + 1];
            float v2 = pj[a * 3 + 2] - sm[OFF_RN + 9 + 2];
            float rv[3];
#pragma unroll
            for (int i = 0; i < 3; ++i)
                rv[i] = sm[OFF_RN + 0 + i] * v0 + sm[OFF_RN + 3 + i] * v1 + sm[OFF_RN + 6 + i] * v2;
            float nr = sqrtf(rv[0] * rv[0] + rv[1] * rv[1] + rv[2] * rv[2]);
            float inv = 1.0f / (nr + 1e-6f);
#pragma unroll
            for (int i = 0; i < 3; ++i) {
                fk[416 + a * 3 + i] = rv[i] * inv;
                fk[431 + a * 3 + i] = rv[i] * 0.1f;
            }
        } else {   // sub == 15: rotation features (R_n^T R_j)
            float e1j[3], e2j[3], e3j[3], tj[3];
            frames_from(pj, e1j, e2j, e3j, tj);
#pragma unroll
            for (int i = 0; i < 3; ++i) {
                float r0 = sm[OFF_RN + 0 + i], r1 = sm[OFF_RN + 3 + i], r2 = sm[OFF_RN + 6 + i];
                fk[446 + i * 3 + 0] = r0 * e1j[0] + r1 * e1j[1] + r2 * e1j[2];
                fk[446 + i * 3 + 1] = r0 * e2j[0] + r1 * e2j[1] + r2 * e2j[2];
                fk[446 + i * 3 + 2] = r0 * e3j[0] + r1 * e3j[1] + r2 * e3j[2];
            }
        }
        __syncthreads();

        // ---------- accumulation: 455-feature projection + rel-embedding row ----------
        float4 acc;
        {
            int rel = smi[OFF_SREL + k];
            float same = sm[OFF_SSAME + k];
            float4 wr = __ldg(reinterpret_cast<const float4*>(Wrel) + rel * 16 + sub);
            acc.x = same * wr.x; acc.y = same * wr.y; acc.z = same * wr.z; acc.w = same * wr.w;
        }
        {
            const float4* wd4 = reinterpret_cast<const float4*>(sm + OFF_WD);
#pragma unroll 7
            for (int f = 0; f < FEATC; ++f) {
                float x = fk[f];
                float4 w = wd4[f * 16 + sub];
                acc.x = fmaf(x, w.x, acc.x);
                acc.y = fmaf(x, w.y, acc.y);
                acc.z = fmaf(x, w.z, acc.z);
                acc.w = fmaf(x, w.w, acc.w);
            }
        }

        // ---------- LayerNorm over P=64 (16-lane butterfly) ----------
        float ssum = acc.x + acc.y + acc.z + acc.w;
        ssum += __shfl_xor_sync(0xffffffffu, ssum, 8);
        ssum += __shfl_xor_sync(0xffffffffu, ssum, 4);
        ssum += __shfl_xor_sync(0xffffffffu, ssum, 2);
        ssum += __shfl_xor_sync(0xffffffffu, ssum, 1);
        float mu = ssum * 0.015625f;
        float d0 = acc.x - mu, d1 = acc.y - mu, d2 = acc.z - mu, d3 = acc.w - mu;
        float sq = d0 * d0 + d1 * d1 + d2 * d2 + d3 * d3;
        sq += __shfl_xor_sync(0xffffffffu, sq, 8);
        sq += __shfl_xor_sync(0xffffffffu, sq, 4);
        sq += __shfl_xor_sync(0xffffffffu, sq, 2);
        sq += __shfl_xor_sync(0xffffffffu, sq, 1);
        float var = sq * 0.015625f;
        float inv = rsqrtf(var + 1e-5f);
        float y0 = lgr[0] * d0 * inv + lbr[0];
        float y1 = lgr[1] * d1 * inv + lbr[1];
        float y2 = lgr[2] * d2 * inv + lbr[2];
        float y3 = lgr[3] * d3 * inv + lbr[3];

        __syncthreads();   // feature reads done -> safe to overwrite region

        // write LN'd pair + restage W2 into reused region
        {
            float* pbw = sm + OFF_PAIR + k * 65 + sub * 4;
            pbw[0] = y0; pbw[1] = y1; pbw[2] = y2; pbw[3] = y3;
        }
        for (int i = tid; i < 128 * 64; i += THREADS) sm[OFF_W2 + i] = W2[i];
        __syncthreads();

        // ---------- MLP layer 1: 64 -> 128, gelu ----------
        float h[8];
#pragma unroll
        for (int j = 0; j < 8; ++j) h[j] = b1r[j];
        {
            const float4* w1v = reinterpret_cast<const float4*>(sm + OFF_W1);
            const float* pb = sm + OFF_PAIR + k * 65;
#pragma unroll 4
            for (int p = 0; p < 64; ++p) {
                float x = pb[p];
                float4 wa = w1v[p * 32 + sub * 2];
                float4 wb = w1v[p * 32 + sub * 2 + 1];
                h[0] = fmaf(x, wa.x, h[0]); h[1] = fmaf(x, wa.y, h[1]);
                h[2] = fmaf(x, wa.z, h[2]); h[3] = fmaf(x, wa.w, h[3]);
                h[4] = fmaf(x, wb.x, h[4]); h[5] = fmaf(x, wb.y, h[5]);
                h[6] = fmaf(x, wb.z, h[6]); h[7] = fmaf(x, wb.w, h[7]);
            }
        }
        {
            float* hb = sm + OFF_H + k * 129 + sub * 8;
#pragma unroll
            for (int j = 0; j < 8; ++j) hb[j] = gelu_f(h[j]);
        }
        __syncthreads();

        // ---------- MLP layer 2: 128 -> 64 ----------
        float4 o;
        o.x = b2r[0]; o.y = b2r[1]; o.z = b2r[2]; o.w = b2r[3];
        {
            const float4* w2v = reinterpret_cast<const float4*>(sm + OFF_W2);
            const float* hr = sm + OFF_H + k * 129;
#pragma unroll 8
            for (int j = 0; j < 128; ++j) {
                float x = hr[j];
                float4 w = w2v[j * 16 + sub];
                o.x = fmaf(x, w.x, o.x);
                o.y = fmaf(x, w.y, o.y);
                o.z = fmaf(x, w.z, o.z);
                o.w = fmaf(x, w.w, o.w);
            }
        }
        reinterpret_cast<float4*>(outPair)[(n * KC + k) * 16 + sub] = o;
        // next-iteration stage syncs provide the barrier before region reuse
    }
}

extern "C" void kernel_launch(void* const* d_in, const int* in_sizes, int n_in,
                              void* d_out, int out_size) {
    const float* pos   = (const float*)d_in[0];
    const float* dmap  = (const float*)d_in[1];
    const int*   nbrs  = (const int*)d_in[2];
    const int*   resi  = (const int*)d_in[3];
    const int*   chain = (const int*)d_in[4];
    const int*   batch = (const int*)d_in[5];
    const float* maskp = (const float*)d_in[6];
    const float* Wrel  = (const float*)d_in[7];
    const float* Wdmap = (const float*)d_in[8];
    const float* Wdist = (const float*)d_in[9];
    const float* Wdir  = (const float*)d_in[10];
    const float* Wrot  = (const float*)d_in[11];
    const float* Wvec  = (const float*)d_in[12];
    const float* lng   = (const float*)d_in[13];
    const float* lnb   = (const float*)d_in[14];
    const float* W1    = (const float*)d_in[15];
    const float* b1    = (const float*)d_in[16];
    const float* W2    = (const float*)d_in[17];
    const float* b2    = (const float*)d_in[18];

    float* outPair = (float*)d_out;
    float* outMask = outPair + (long)Ntot * KC * PC;

    cudaFuncSetAttribute(dsd_kernel, cudaFuncAttributeMaxDynamicSharedMemorySize, SMEMF * 4);
    int sms = 148;
    cudaDeviceGetAttribute(&sms, cudaDevAttrMultiProcessorCount, 0);

    dsd_kernel<<<sms, THREADS, SMEMF * 4>>>(
        pos, dmap, nbrs, resi, chain, batch, maskp,
        Wrel, Wdmap, Wdist, Wdir, Wrot, Wvec, lng, lnb, W1, b1, W2, b2,
        outPair, outMask);
}

// round 4
// speedup vs baseline: 1.9519x; 1.9519x over previous
#include <cuda_runtime.h>
#include <math.h>

#define Ntot 8192
#define KC   32
#define PC   64
#define FEATC 455
#define FSC   457          // odd stride -> conflict-free lane-k scalar access
#define THREADS 512

// ---- shared memory layout (float offsets) ----
#define OFF_WD    0                        // 455*64 = 29120
#define OFF_W1    29120                    // 64*128 = 8192
#define OFF_R     37312                    // reused: features 32*457=14624  OR  W2(8192)+H(4128)
#define OFF_W2    (OFF_R)                  // 128*64 = 8192
#define OFF_H     (OFF_R + 8192)           // 32*129 = 4128
#define OFF_PART0 (OFF_R + 14624)          // 32*65 = 2080 (also holds LN'd pair)
#define OFF_PART1 (OFF_PART0 + 2080)       // 32*65 = 2080
#define OFF_PJ    (OFF_PART1 + 2080)       // 32*16 = 512
#define OFF_POSN  (OFF_PJ + 512)           // 16
#define OFF_RN    (OFF_POSN + 16)          // 12
#define OFF_SJ    (OFF_RN + 12)            // 32 ints
#define OFF_SREL  (OFF_SJ + 32)
#define OFF_SSAME (OFF_SREL + 32)
#define OFF_SPM   (OFF_SSAME + 32)
#define SMEMF     (OFF_SPM + 32)           // 56764 floats = 227056 bytes

// ---------------- RBF: 16 bins with only 3 exps ----------------
__device__ __forceinline__ void rbf16(float d, float* out) {
    const float SI = 0.72727272727f;   // 16/22
    const float G  = 1.06666666667f;   // 16/15
    const float Q  = 0.10273954f;      // exp(-2*G*G)
    float g = d * SI;
    int m = __float2int_rn(g * 0.9375f);
    m = m < 0 ? 0 : (m > 15 ? 15 : m);
    float u = g - (float)m * G;
    float peak = __expf(-u * u);
    float r = __expf(G * (2.0f * u - G));
    float s = __expf(-G * (2.0f * u + G));
    out[m] = peak;
    float v = peak;
#pragma unroll
    for (int st = 1; st <= 15; ++st) {
        v *= r; r *= Q;
        int i = m + st;
        if (i <= 15) out[i] = v;
    }
    v = peak;
#pragma unroll
    for (int st = 1; st <= 15; ++st) {
        v *= s; s *= Q;
        int i = m - st;
        if (i >= 0) out[i] = v;
    }
}

__device__ __forceinline__ void frames_from(const float* p,
                                            float e1[3], float e2[3], float e3[3], float t[3]) {
    t[0] = p[3]; t[1] = p[4]; t[2] = p[5];
    float v1x = p[6] - t[0], v1y = p[7] - t[1], v1z = p[8] - t[2];
    float v2x = p[0] - t[0], v2y = p[1] - t[1], v2z = p[2] - t[2];
    float n1 = sqrtf(v1x * v1x + v1y * v1y + v1z * v1z) + 1e-6f;
    e1[0] = v1x / n1; e1[1] = v1y / n1; e1[2] = v1z / n1;
    float dt = v2x * e1[0] + v2y * e1[1] + v2z * e1[2];
    float ux = v2x - dt * e1[0], uy = v2y - dt * e1[1], uz = v2z - dt * e1[2];
    float n2 = sqrtf(ux * ux + uy * uy + uz * uz) + 1e-6f;
    e2[0] = ux / n2; e2[1] = uy / n2; e2[2] = uz / n2;
    e3[0] = e1[1] * e2[2] - e1[2] * e2[1];
    e3[1] = e1[2] * e2[0] - e1[0] * e2[2];
    e3[2] = e1[0] * e2[1] - e1[1] * e2[0];
}

__device__ __forceinline__ float gelu_f(float x) {
    float c = x + 0.044715f * x * x * x;
    return 0.5f * x * (1.0f + tanhf(0.7978845608028654f * c));
}

__global__ void __launch_bounds__(THREADS, 1)
dsd_kernel(const float* __restrict__ pos, const float* __restrict__ dmap,
           const int* __restrict__ nbrs, const int* __restrict__ resi,
           const int* __restrict__ chain, const int* __restrict__ batch,
           const float* __restrict__ maskp,
           const float* __restrict__ Wrel, const float* __restrict__ Wdmap,
           const float* __restrict__ Wdist, const float* __restrict__ Wdir,
           const float* __restrict__ Wrot, const float* __restrict__ Wvec,
           const float* __restrict__ lng, const float* __restrict__ lnb,
           const float* __restrict__ W1, const float* __restrict__ b1,
           const float* __restrict__ W2, const float* __restrict__ b2,
           float* __restrict__ outPair, float* __restrict__ outMask)
{
    extern __shared__ float sm[];
    const int tid = threadIdx.x;
    // accumulation layout: warp = 32 k-lanes at fixed (h, s8)
    const int k   = tid & 31;         // lane
    const int s8  = (tid >> 5) & 7;   // output col group (8 cols)
    const int h   = tid >> 8;         // feature-half
    const int worker = h * 8 + s8;    // 0..15, warp-uniform: feature-build role
    // LN layout
    const int lkk = tid >> 4;         // 0..31
    const int ls  = tid & 15;         // 0..15 (4 cols each)
    // MLP layout
    const int g   = tid >> 5;         // 0..15

    // ---- stage constant weights once ----
    for (int i = tid; i < 400 * 64; i += THREADS) sm[OFF_WD + i] = Wdist[i];
    for (int i = tid; i < 16 * 64; i += THREADS) sm[OFF_WD + 400 * 64 + i] = Wdmap[i];
    for (int i = tid; i < 15 * 64; i += THREADS) sm[OFF_WD + 416 * 64 + i] = Wdir[i];
    for (int i = tid; i < 15 * 64; i += THREADS) sm[OFF_WD + 431 * 64 + i] = Wvec[i];
    for (int i = tid; i < 9 * 64; i += THREADS) sm[OFF_WD + 446 * 64 + i] = Wrot[i];
    for (int i = tid; i < 64 * 128; i += THREADS) sm[OFF_W1 + i] = W1[i];

    float lgr[4], lbr[4], b2r[4], b1r[8];
#pragma unroll
    for (int i = 0; i < 4; ++i) {
        lgr[i] = lng[ls * 4 + i];
        lbr[i] = lnb[ls * 4 + i];
        b2r[i] = b2[g * 4 + i];
    }
#pragma unroll
    for (int i = 0; i < 8; ++i) b1r[i] = b1[g * 8 + i];

    __syncthreads();

    int* smi = (int*)sm;

    for (int n = blockIdx.x; n < Ntot; n += gridDim.x) {
        // ---------- stage 1: meta, frame of n, pos of n ----------
        if (tid < 32) {
            int nb = nbrs[n * KC + tid];
            int j = nb < 0 ? 0 : nb;
            float valid = (nb != -1) ? 1.0f : 0.0f;
            smi[OFF_SJ + tid] = j;
            int dr = resi[j] - resi[n];
            dr = dr < -32 ? -32 : (dr > 32 ? 32 : dr);
            smi[OFF_SREL + tid] = dr + 32;
            float same = (chain[j] == chain[n] && batch[j] == batch[n]) ? 1.0f : 0.0f;
            sm[OFF_SSAME + tid] = same;
            float pm = maskp[n] * maskp[j] * valid;
            sm[OFF_SPM + tid] = pm;
            outMask[n * KC + tid] = pm;
        } else if (tid == 32) {
            float e1[3], e2[3], e3[3], t[3], prow[9];
#pragma unroll
            for (int i = 0; i < 9; ++i) prow[i] = pos[n * 15 + i];
            frames_from(prow, e1, e2, e3, t);
#pragma unroll
            for (int r = 0; r < 3; ++r) {
                sm[OFF_RN + r * 3 + 0] = e1[r];
                sm[OFF_RN + r * 3 + 1] = e2[r];
                sm[OFF_RN + r * 3 + 2] = e3[r];
            }
            sm[OFF_RN + 9 + 0] = t[0]; sm[OFF_RN + 9 + 1] = t[1]; sm[OFF_RN + 9 + 2] = t[2];
        } else if (tid >= 64 && tid < 79) {
            sm[OFF_POSN + tid - 64] = pos[n * 15 + (tid - 64)];
        }
        __syncthreads();

        // ---------- stage 2: gather neighbor positions ----------
        if (tid < 480) {
            int kk = tid / 15, e = tid - kk * 15;
            int j = smi[OFF_SJ + kk];
            sm[OFF_PJ + kk * 16 + e] = pos[j * 15 + e];
        }
        __syncthreads();

        // ---------- stage 3: build features (worker is warp-uniform) ----------
        float* fk = sm + OFF_R + k * FSC;
        const float* pn = sm + OFF_POSN;
        const float* pj = sm + OFF_PJ + k * 16;
        {   // task A: distance pair dp = worker (0..15)
            int a = worker / 5, b = worker - a * 5;
            float dx = pn[a * 3 + 0] - pj[b * 3 + 0];
            float dy = pn[a * 3 + 1] - pj[b * 3 + 1];
            float dz = pn[a * 3 + 2] - pj[b * 3 + 2];
            float d = sqrtf(dx * dx + dy * dy + dz * dz);
            rbf16(d, fk + worker * 16);
        }
        if (worker < 9) {   // task B: dp = 16 + worker
            int dp = 16 + worker;
            int a = dp / 5, b = dp - a * 5;
            float dx = pn[a * 3 + 0] - pj[b * 3 + 0];
            float dy = pn[a * 3 + 1] - pj[b * 3 + 1];
            float dz = pn[a * 3 + 2] - pj[b * 3 + 2];
            float d = sqrtf(dx * dx + dy * dy + dz * dz);
            rbf16(d, fk + dp * 16);
        } else if (worker == 9) {   // dmap rbf, masked
            int j = smi[OFF_SJ + k];
            float pm = sm[OFF_SPM + k];
            float dval = __ldg(&dmap[(long)n * Ntot + j]);
            if (pm > 0.0f) {
                rbf16(dval, fk + 400);
            } else {
#pragma unroll
                for (int i = 0; i < 16; ++i) fk[400 + i] = 0.0f;
            }
        } else if (worker < 15) {   // rel_vec + dirs for atom a = worker-10
            int a = worker - 10;
            float v0 = pj[a * 3 + 0] - sm[OFF_RN + 9 + 0];
            float v1 = pj[a * 3 + 1] - sm[OFF_RN + 9 + 1];
            float v2 = pj[a * 3 + 2] - sm[OFF_RN + 9 + 2];
            float rv[3];
#pragma unroll
            for (int i = 0; i < 3; ++i)
                rv[i] = sm[OFF_RN + 0 + i] * v0 + sm[OFF_RN + 3 + i] * v1 + sm[OFF_RN + 6 + i] * v2;
            float nr = sqrtf(rv[0] * rv[0] + rv[1] * rv[1] + rv[2] * rv[2]);
            float inv = 1.0f / (nr + 1e-6f);
#pragma unroll
            for (int i = 0; i < 3; ++i) {
                fk[416 + a * 3 + i] = rv[i] * inv;
                fk[431 + a * 3 + i] = rv[i] * 0.1f;
            }
        } else {   // worker == 15: rotation features R_n^T R_j
            float e1j[3], e2j[3], e3j[3], tj[3];
            frames_from(pj, e1j, e2j, e3j, tj);
#pragma unroll
            for (int i = 0; i < 3; ++i) {
                float r0 = sm[OFF_RN + 0 + i], r1 = sm[OFF_RN + 3 + i], r2 = sm[OFF_RN + 6 + i];
                fk[446 + i * 3 + 0] = r0 * e1j[0] + r1 * e1j[1] + r2 * e1j[2];
                fk[446 + i * 3 + 1] = r0 * e2j[0] + r1 * e2j[1] + r2 * e2j[2];
                fk[446 + i * 3 + 2] = r0 * e3j[0] + r1 * e3j[1] + r2 * e3j[2];
            }
        }
        __syncthreads();

        // ---------- stage 4: feature projection (r=8, feature-split halves) ----------
        {
            float acc[8];
#pragma unroll
            for (int j = 0; j < 8; ++j) acc[j] = 0.0f;
            const int fbeg = h ? 228 : 0;
            const int fend = h ? 455 : 228;
            const float4* w4 = reinterpret_cast<const float4*>(sm + OFF_WD) + s8 * 2;
            const float* x = sm + OFF_R + k * FSC;
#pragma unroll 4
            for (int f = fbeg; f < fend; ++f) {
                float xv = x[f];
                float4 wa = w4[f * 16];
                float4 wb = w4[f * 16 + 1];
                acc[0] = fmaf(xv, wa.x, acc[0]); acc[1] = fmaf(xv, wa.y, acc[1]);
                acc[2] = fmaf(xv, wa.z, acc[2]); acc[3] = fmaf(xv, wa.w, acc[3]);
                acc[4] = fmaf(xv, wb.x, acc[4]); acc[5] = fmaf(xv, wb.y, acc[5]);
                acc[6] = fmaf(xv, wb.z, acc[6]); acc[7] = fmaf(xv, wb.w, acc[7]);
            }
            float* pp = sm + (h ? OFF_PART1 : OFF_PART0) + k * 65 + s8 * 8;
#pragma unroll
            for (int j = 0; j < 8; ++j) pp[j] = acc[j];
        }
        __syncthreads();

        // ---------- stage 5: combine + Wrel + LayerNorm (remap to (kk, s)) ----------
        {
            float v0 = sm[OFF_PART0 + lkk * 65 + ls * 4 + 0] + sm[OFF_PART1 + lkk * 65 + ls * 4 + 0];
            float v1 = sm[OFF_PART0 + lkk * 65 + ls * 4 + 1] + sm[OFF_PART1 + lkk * 65 + ls * 4 + 1];
            float v2 = sm[OFF_PART0 + lkk * 65 + ls * 4 + 2] + sm[OFF_PART1 + lkk * 65 + ls * 4 + 2];
            float v3 = sm[OFF_PART0 + lkk * 65 + ls * 4 + 3] + sm[OFF_PART1 + lkk * 65 + ls * 4 + 3];
            int rel = smi[OFF_SREL + lkk];
            float same = sm[OFF_SSAME + lkk];
            float4 wr = __ldg(reinterpret_cast<const float4*>(Wrel) + rel * 16 + ls);
            v0 = fmaf(same, wr.x, v0); v1 = fmaf(same, wr.y, v1);
            v2 = fmaf(same, wr.z, v2); v3 = fmaf(same, wr.w, v3);

            float ssum = v0 + v1 + v2 + v3;
            ssum += __shfl_xor_sync(0xffffffffu, ssum, 8);
            ssum += __shfl_xor_sync(0xffffffffu, ssum, 4);
            ssum += __shfl_xor_sync(0xffffffffu, ssum, 2);
            ssum += __shfl_xor_sync(0xffffffffu, ssum, 1);
            float mu = ssum * 0.015625f;
            float d0 = v0 - mu, d1 = v1 - mu, d2 = v2 - mu, d3 = v3 - mu;
            float sq = d0 * d0 + d1 * d1 + d2 * d2 + d3 * d3;
            sq += __shfl_xor_sync(0xffffffffu, sq, 8);
            sq += __shfl_xor_sync(0xffffffffu, sq, 4);
            sq += __shfl_xor_sync(0xffffffffu, sq, 2);
            sq += __shfl_xor_sync(0xffffffffu, sq, 1);
            float var = sq * 0.015625f;
            float inv = rsqrtf(var + 1e-5f);
            sm[OFF_PART0 + lkk * 65 + ls * 4 + 0] = lgr[0] * d0 * inv + lbr[0];
            sm[OFF_PART0 + lkk * 65 + ls * 4 + 1] = lgr[1] * d1 * inv + lbr[1];
            sm[OFF_PART0 + lkk * 65 + ls * 4 + 2] = lgr[2] * d2 * inv + lbr[2];
            sm[OFF_PART0 + lkk * 65 + ls * 4 + 3] = lgr[3] * d3 * inv + lbr[3];
        }
        // restage W2 into reused region (features are dead now)
        for (int i = tid; i < 128 * 64; i += THREADS) sm[OFF_W2 + i] = W2[i];
        __syncthreads();

        // ---------- stage 6: MLP layer 1 (64 -> 128, r=8, warp = 32 k) ----------
        {
            float hv[8];
#pragma unroll
            for (int j = 0; j < 8; ++j) hv[j] = b1r[j];
            const float* pb = sm + OFF_PART0 + k * 65;
            const float4* w1v = reinterpret_cast<const float4*>(sm + OFF_W1) + g * 2;
#pragma unroll 4
            for (int p = 0; p < 64; ++p) {
                float xv = pb[p];
                float4 wa = w1v[p * 32];
                float4 wb = w1v[p * 32 + 1];
                hv[0] = fmaf(xv, wa.x, hv[0]); hv[1] = fmaf(xv, wa.y, hv[1]);
                hv[2] = fmaf(xv, wa.z, hv[2]); hv[3] = fmaf(xv, wa.w, hv[3]);
                hv[4] = fmaf(xv, wb.x, hv[4]); hv[5] = fmaf(xv, wb.y, hv[5]);
                hv[6] = fmaf(xv, wb.z, hv[6]); hv[7] = fmaf(xv, wb.w, hv[7]);
            }
            float* hb = sm + OFF_H + k * 129 + g * 8;
#pragma unroll
            for (int j = 0; j < 8; ++j) hb[j] = gelu_f(hv[j]);
        }
        __syncthreads();

        // ---------- stage 7: MLP layer 2 (128 -> 64, r=4, warp = 32 k) ----------
        {
            float4 o;
            o.x = b2r[0]; o.y = b2r[1]; o.z = b2r[2]; o.w = b2r[3];
            const float* hr = sm + OFF_H + k * 129;
            const float4* w2v = reinterpret_cast<const float4*>(sm + OFF_W2) + g;
#pragma unroll 8
            for (int j = 0; j < 128; ++j) {
                float xv = hr[j];
                float4 w = w2v[j * 16];
                o.x = fmaf(xv, w.x, o.x);
                o.y = fmaf(xv, w.y, o.y);
                o.z = fmaf(xv, w.z, o.z);
                o.w = fmaf(xv, w.w, o.w);
            }
            reinterpret_cast<float4*>(outPair)[(n * KC + k) * 16 + g] = o;
        }
        // loop-top syncs order region reuse for the next n
    }
}

extern "C" void kernel_launch(void* const* d_in, const int* in_sizes, int n_in,
                              void* d_out, int out_size) {
    const float* pos   = (const float*)d_in[0];
    const float* dmap  = (const float*)d_in[1];
    const int*   nbrs  = (const int*)d_in[2];
    const int*   resi  = (const int*)d_in[3];
    const int*   chain = (const int*)d_in[4];
    const int*   batch = (const int*)d_in[5];
    const float* maskp = (const float*)d_in[6];
    const float* Wrel  = (const float*)d_in[7];
    const float* Wdmap = (const float*)d_in[8];
    const float* Wdist = (const float*)d_in[9];
    const float* Wdir  = (const float*)d_in[10];
    const float* Wrot  = (const float*)d_in[11];
    const float* Wvec  = (const float*)d_in[12];
    const float* lng   = (const float*)d_in[13];
    const float* lnb   = (const float*)d_in[14];
    const float* W1    = (const float*)d_in[15];
    const float* b1    = (const float*)d_in[16];
    const float* W2    = (const float*)d_in[17];
    const float* b2    = (const float*)d_in[18];

    float* outPair = (float*)d_out;
    float* outMask = outPair + (long)Ntot * KC * PC;

    cudaFuncSetAttribute(dsd_kernel, cudaFuncAttributeMaxDynamicSharedMemorySize, SMEMF * 4);
    int sms = 148;
    cudaDeviceGetAttribute(&sms, cudaDevAttrMultiProcessorCount, 0);

    dsd_kernel<<<sms, THREADS, SMEMF * 4>>>(
        pos, dmap, nbrs, resi, chain, batch, maskp,
        Wrel, Wdmap, Wdist, Wdir, Wrot, Wvec, lng, lnb, W1, b1, W2, b2,
        outPair, outMask);
}

// round 5
// speedup vs baseline: 2.0254x; 1.0377x over previous
#include <cuda_runtime.h>
#include <math.h>

typedef unsigned long long ull;

#define Ntot 8192
#define KC   32
#define PC   64
#define FEATC 455
#define FSC   457          // odd stride -> conflict-free lane-k scalar access
#define THREADS 512

// ---- shared memory layout (float offsets) ----
#define OFF_WD    0                        // 455*64 = 29120
#define OFF_W1    29120                    // 64*128 = 8192
#define OFF_R     37312                    // reused: features 32*457=14624  OR  W2(8192)+H(4128)
#define OFF_W2    (OFF_R)                  // 128*64 = 8192
#define OFF_H     (OFF_R + 8192)           // 32*129 = 4128
#define OFF_PART0 (OFF_R + 14624)          // 32*66 = 2112 (stride 66, 8B-aligned rows)
#define OFF_PART1 (OFF_PART0 + 2112)       // 32*66 = 2112 ; later reused as LN'd pair (stride 65)
#define OFF_PJ    (OFF_PART1 + 2112)       // 32*16 = 512
#define OFF_POSN  (OFF_PJ + 512)           // 16
#define OFF_RN    (OFF_POSN + 16)          // 12
#define OFF_SJ    (OFF_RN + 12)            // 32 ints
#define OFF_SREL  (OFF_SJ + 32)
#define OFF_SSAME (OFF_SREL + 32)
#define OFF_SPM   (OFF_SSAME + 32)
#define SMEMF     (OFF_SPM + 32)           // 56828 floats = 227312 bytes

// ---- packed f32x2 helpers (Blackwell FFMA2 path) ----
#define FMA2(d, a, b, c) asm("fma.rn.f32x2 %0, %1, %2, %3;" : "=l"(d) : "l"(a), "l"(b), "l"(c))
#define ADD2(d, a, b)    asm("add.rn.f32x2 %0, %1, %2;"     : "=l"(d) : "l"(a), "l"(b))
#define PK2(r, x)        asm("mov.b64 %0, {%1, %1};"        : "=l"(r) : "f"(x))
#define PK2D(r, x, y)    asm("mov.b64 %0, {%1, %2};"        : "=l"(r) : "f"(x), "f"(y))
#define UPK2(lo, hi, v)  asm("mov.b64 {%0, %1}, %2;"        : "=f"(lo), "=f"(hi) : "l"(v))

// ---------------- RBF: 16 bins with only 3 exps ----------------
__device__ __forceinline__ void rbf16(float d, float* out) {
    const float SI = 0.72727272727f;   // 16/22
    const float G  = 1.06666666667f;   // 16/15
    const float Q  = 0.10273954f;      // exp(-2*G*G)
    float g = d * SI;
    int m = __float2int_rn(g * 0.9375f);
    m = m < 0 ? 0 : (m > 15 ? 15 : m);
    float u = g - (float)m * G;
    float peak = __expf(-u * u);
    float r = __expf(G * (2.0f * u - G));
    float s = __expf(-G * (2.0f * u + G));
    out[m] = peak;
    float v = peak;
#pragma unroll
    for (int st = 1; st <= 15; ++st) {
        v *= r; r *= Q;
        int i = m + st;
        if (i <= 15) out[i] = v;
    }
    v = peak;
#pragma unroll
    for (int st = 1; st <= 15; ++st) {
        v *= s; s *= Q;
        int i = m - st;
        if (i >= 0) out[i] = v;
    }
}

__device__ __forceinline__ void frames_from(const float* p,
                                            float e1[3], float e2[3], float e3[3], float t[3]) {
    t[0] = p[3]; t[1] = p[4]; t[2] = p[5];
    float v1x = p[6] - t[0], v1y = p[7] - t[1], v1z = p[8] - t[2];
    float v2x = p[0] - t[0], v2y = p[1] - t[1], v2z = p[2] - t[2];
    float n1 = sqrtf(v1x * v1x + v1y * v1y + v1z * v1z) + 1e-6f;
    e1[0] = v1x / n1; e1[1] = v1y / n1; e1[2] = v1z / n1;
    float dt = v2x * e1[0] + v2y * e1[1] + v2z * e1[2];
    float ux = v2x - dt * e1[0], uy = v2y - dt * e1[1], uz = v2z - dt * e1[2];
    float n2 = sqrtf(ux * ux + uy * uy + uz * uz) + 1e-6f;
    e2[0] = ux / n2; e2[1] = uy / n2; e2[2] = uz / n2;
    e3[0] = e1[1] * e2[2] - e1[2] * e2[1];
    e3[1] = e1[2] * e2[0] - e1[0] * e2[2];
    e3[2] = e1[0] * e2[1] - e1[1] * e2[0];
}

__device__ __forceinline__ float gelu_f(float x) {
    float c = x + 0.044715f * x * x * x;
    return 0.5f * x * (1.0f + tanhf(0.7978845608028654f * c));
}

__global__ void __launch_bounds__(THREADS, 1)
dsd_kernel(const float* __restrict__ pos, const float* __restrict__ dmap,
           const int* __restrict__ nbrs, const int* __restrict__ resi,
           const int* __restrict__ chain, const int* __restrict__ batch,
           const float* __restrict__ maskp,
           const float* __restrict__ Wrel, const float* __restrict__ Wdmap,
           const float* __restrict__ Wdist, const float* __restrict__ Wdir,
           const float* __restrict__ Wrot, const float* __restrict__ Wvec,
           const float* __restrict__ lng, const float* __restrict__ lnb,
           const float* __restrict__ W1, const float* __restrict__ b1,
           const float* __restrict__ W2, const float* __restrict__ b2,
           float* __restrict__ outPair, float* __restrict__ outMask)
{
    extern __shared__ float sm[];
    const int tid = threadIdx.x;
    const int k   = tid & 31;         // lane = neighbor slot
    const int wid = tid >> 5;         // warp id = worker id (0..15)
    const int pg  = wid & 3;          // p-group (16 cols each)
    const int fq  = wid >> 2;         // feature quarter (0..3)
    // LN layout
    const int lkk = tid >> 4;         // 0..31
    const int ls  = tid & 15;         // 0..15 (4 cols each)
    // MLP layout
    const int g   = wid;              // 0..15

    // ---- stage constant weights once ----
    for (int i = tid; i < 400 * 64; i += THREADS) sm[OFF_WD + i] = Wdist[i];
    for (int i = tid; i < 16 * 64; i += THREADS) sm[OFF_WD + 400 * 64 + i] = Wdmap[i];
    for (int i = tid; i < 15 * 64; i += THREADS) sm[OFF_WD + 416 * 64 + i] = Wdir[i];
    for (int i = tid; i < 15 * 64; i += THREADS) sm[OFF_WD + 431 * 64 + i] = Wvec[i];
    for (int i = tid; i < 9 * 64; i += THREADS) sm[OFF_WD + 446 * 64 + i] = Wrot[i];
    for (int i = tid; i < 64 * 128; i += THREADS) sm[OFF_W1 + i] = W1[i];

    float lgr[4], lbr[4];
    ull b1p[4], b2p[2];
#pragma unroll
    for (int i = 0; i < 4; ++i) {
        lgr[i] = lng[ls * 4 + i];
        lbr[i] = lnb[ls * 4 + i];
    }
#pragma unroll
    for (int i = 0; i < 4; ++i) { float a = b1[g * 8 + 2 * i], b = b1[g * 8 + 2 * i + 1]; PK2D(b1p[i], a, b); }
#pragma unroll
    for (int i = 0; i < 2; ++i) { float a = b2[g * 4 + 2 * i], b = b2[g * 4 + 2 * i + 1]; PK2D(b2p[i], a, b); }

    const int fbeg = fq * 114;
    const int fend = (fq == 3) ? 455 : (fbeg + 114);

    __syncthreads();

    int* smi = (int*)sm;

    for (int n = blockIdx.x; n < Ntot; n += gridDim.x) {
        // ---------- stage 1: meta, frame of n, pos of n ----------
        if (tid < 32) {
            int nb = nbrs[n * KC + tid];
            int j = nb < 0 ? 0 : nb;
            float valid = (nb != -1) ? 1.0f : 0.0f;
            smi[OFF_SJ + tid] = j;
            int dr = resi[j] - resi[n];
            dr = dr < -32 ? -32 : (dr > 32 ? 32 : dr);
            smi[OFF_SREL + tid] = dr + 32;
            float same = (chain[j] == chain[n] && batch[j] == batch[n]) ? 1.0f : 0.0f;
            sm[OFF_SSAME + tid] = same;
            float pm = maskp[n] * maskp[j] * valid;
            sm[OFF_SPM + tid] = pm;
            outMask[n * KC + tid] = pm;
        } else if (tid == 32) {
            float e1[3], e2[3], e3[3], t[3], prow[9];
#pragma unroll
            for (int i = 0; i < 9; ++i) prow[i] = pos[n * 15 + i];
            frames_from(prow, e1, e2, e3, t);
#pragma unroll
            for (int r = 0; r < 3; ++r) {
                sm[OFF_RN + r * 3 + 0] = e1[r];
                sm[OFF_RN + r * 3 + 1] = e2[r];
                sm[OFF_RN + r * 3 + 2] = e3[r];
            }
            sm[OFF_RN + 9 + 0] = t[0]; sm[OFF_RN + 9 + 1] = t[1]; sm[OFF_RN + 9 + 2] = t[2];
        } else if (tid >= 64 && tid < 79) {
            sm[OFF_POSN + tid - 64] = pos[n * 15 + (tid - 64)];
        }
        __syncthreads();

        // ---------- stage 2: gather neighbor positions ----------
        if (tid < 480) {
            int kk = tid / 15, e = tid - kk * 15;
            int j = smi[OFF_SJ + kk];
            sm[OFF_PJ + kk * 16 + e] = pos[j * 15 + e];
        }
        __syncthreads();

        // ---------- stage 3: build features (wid is warp-uniform) ----------
        {
            float* fk = sm + OFF_R + k * FSC;
            const float* pn = sm + OFF_POSN;
            const float* pj = sm + OFF_PJ + k * 16;
            {   // task A: distance pair dp = wid (0..15)
                int a = wid / 5, b = wid - a * 5;
                float dx = pn[a * 3 + 0] - pj[b * 3 + 0];
                float dy = pn[a * 3 + 1] - pj[b * 3 + 1];
                float dz = pn[a * 3 + 2] - pj[b * 3 + 2];
                float d = sqrtf(dx * dx + dy * dy + dz * dz);
                rbf16(d, fk + wid * 16);
            }
            if (wid < 9) {   // task B: dp = 16 + wid
                int dp = 16 + wid;
                int a = dp / 5, b = dp - a * 5;
                float dx = pn[a * 3 + 0] - pj[b * 3 + 0];
                float dy = pn[a * 3 + 1] - pj[b * 3 + 1];
                float dz = pn[a * 3 + 2] - pj[b * 3 + 2];
                float d = sqrtf(dx * dx + dy * dy + dz * dz);
                rbf16(d, fk + dp * 16);
            } else if (wid == 9) {   // dmap rbf, masked
                int j = smi[OFF_SJ + k];
                float pm = sm[OFF_SPM + k];
                float dval = __ldg(&dmap[(long)n * Ntot + j]);
                if (pm > 0.0f) {
                    rbf16(dval, fk + 400);
                } else {
#pragma unroll
                    for (int i = 0; i < 16; ++i) fk[400 + i] = 0.0f;
                }
            } else if (wid < 15) {   // rel_vec + dirs for atom a = wid-10
                int a = wid - 10;
                float v0 = pj[a * 3 + 0] - sm[OFF_RN + 9 + 0];
                float v1 = pj[a * 3 + 1] - sm[OFF_RN + 9 + 1];
                float v2 = pj[a * 3 + 2] - sm[OFF_RN + 9 + 2];
                float rv[3];
#pragma unroll
                for (int i = 0; i < 3; ++i)
                    rv[i] = sm[OFF_RN + 0 + i] * v0 + sm[OFF_RN + 3 + i] * v1 + sm[OFF_RN + 6 + i] * v2;
                float nr = sqrtf(rv[0] * rv[0] + rv[1] * rv[1] + rv[2] * rv[2]);
                float inv = 1.0f / (nr + 1e-6f);
#pragma unroll
                for (int i = 0; i < 3; ++i) {
                    fk[416 + a * 3 + i] = rv[i] * inv;
                    fk[431 + a * 3 + i] = rv[i] * 0.1f;
                }
            } else {   // wid == 15: rotation features R_n^T R_j
                float e1j[3], e2j[3], e3j[3], tj[3];
                frames_from(pj, e1j, e2j, e3j, tj);
#pragma unroll
                for (int i = 0; i < 3; ++i) {
                    float r0 = sm[OFF_RN + 0 + i], r1 = sm[OFF_RN + 3 + i], r2 = sm[OFF_RN + 6 + i];
                    fk[446 + i * 3 + 0] = r0 * e1j[0] + r1 * e1j[1] + r2 * e1j[2];
                    fk[446 + i * 3 + 1] = r0 * e2j[0] + r1 * e2j[1] + r2 * e2j[2];
                    fk[446 + i * 3 + 2] = r0 * e3j[0] + r1 * e3j[1] + r2 * e3j[2];
                }
            }
        }
        __syncthreads();

        // ---------- stage 4: feature projection, t_p=16, f-split=4, FFMA2 ----------
        ull acc[8];
#pragma unroll
        for (int j = 0; j < 8; ++j) acc[j] = 0ull;
        {
            const float* x = sm + OFF_R + k * FSC;
            const ulonglong2* w = reinterpret_cast<const ulonglong2*>(sm + OFF_WD) + pg * 4;
#pragma unroll 2
            for (int f = fbeg; f < fend; ++f) {
                float xv = x[f];
                ull xx; PK2(xx, xv);
                ulonglong2 u0 = w[f * 16 + 0];
                ulonglong2 u1 = w[f * 16 + 1];
                ulonglong2 u2 = w[f * 16 + 2];
                ulonglong2 u3 = w[f * 16 + 3];
                FMA2(acc[0], xx, u0.x, acc[0]); FMA2(acc[1], xx, u0.y, acc[1]);
                FMA2(acc[2], xx, u1.x, acc[2]); FMA2(acc[3], xx, u1.y, acc[3]);
                FMA2(acc[4], xx, u2.x, acc[4]); FMA2(acc[5], xx, u2.y, acc[5]);
                FMA2(acc[6], xx, u3.x, acc[6]); FMA2(acc[7], xx, u3.y, acc[7]);
            }
        }
        // fq0 -> PART0, fq1 -> PART1 (plain store); then fq2/fq3 add into them
        if (fq < 2) {
            ull* pb = (ull*)(sm + (fq == 0 ? OFF_PART0 : OFF_PART1)) + k * 33 + pg * 8;
#pragma unroll
            for (int j = 0; j < 8; ++j) pb[j] = acc[j];
        }
        __syncthreads();
        if (fq >= 2) {
            ull* pb = (ull*)(sm + (fq == 2 ? OFF_PART0 : OFF_PART1)) + k * 33 + pg * 8;
#pragma unroll
            for (int j = 0; j < 8; ++j) {
                ull t = pb[j];
                ADD2(t, t, acc[j]);
                pb[j] = t;
            }
        }
        // restage W2 into reused region (features are dead now)
        for (int i = tid; i < 128 * 64; i += THREADS) sm[OFF_W2 + i] = W2[i];
        __syncthreads();

        // ---------- stage 5: combine + Wrel + LayerNorm ----------
        {
            float v0 = sm[OFF_PART0 + lkk * 66 + ls * 4 + 0] + sm[OFF_PART1 + lkk * 66 + ls * 4 + 0];
            float v1 = sm[OFF_PART0 + lkk * 66 + ls * 4 + 1] + sm[OFF_PART1 + lkk * 66 + ls * 4 + 1];
            float v2 = sm[OFF_PART0 + lkk * 66 + ls * 4 + 2] + sm[OFF_PART1 + lkk * 66 + ls * 4 + 2];
            float v3 = sm[OFF_PART0 + lkk * 66 + ls * 4 + 3] + sm[OFF_PART1 + lkk * 66 + ls * 4 + 3];
            int rel = smi[OFF_SREL + lkk];
            float same = sm[OFF_SSAME + lkk];
            float4 wr = __ldg(reinterpret_cast<const float4*>(Wrel) + rel * 16 + ls);
            v0 = fmaf(same, wr.x, v0); v1 = fmaf(same, wr.y, v1);
            v2 = fmaf(same, wr.z, v2); v3 = fmaf(same, wr.w, v3);
            __syncthreads();   // all PART reads done before pair overwrite below

            float ssum = v0 + v1 + v2 + v3;
            ssum += __shfl_xor_sync(0xffffffffu, ssum, 8);
            ssum += __shfl_xor_sync(0xffffffffu, ssum, 4);
            ssum += __shfl_xor_sync(0xffffffffu, ssum, 2);
            ssum += __shfl_xor_sync(0xffffffffu, ssum, 1);
            float mu = ssum * 0.015625f;
            float d0 = v0 - mu, d1 = v1 - mu, d2 = v2 - mu, d3 = v3 - mu;
            float sq = d0 * d0 + d1 * d1 + d2 * d2 + d3 * d3;
            sq += __shfl_xor_sync(0xffffffffu, sq, 8);
            sq += __shfl_xor_sync(0xffffffffu, sq, 4);
            sq += __shfl_xor_sync(0xffffffffu, sq, 2);
            sq += __shfl_xor_sync(0xffffffffu, sq, 1);
            float var = sq * 0.015625f;
            float inv = rsqrtf(var + 1e-5f);
            // LN'd pair -> PART1 region with stride 65 (conflict-free MLP x reads)
            sm[OFF_PART1 + lkk * 65 + ls * 4 + 0] = lgr[0] * d0 * inv + lbr[0];
            sm[OFF_PART1 + lkk * 65 + ls * 4 + 1] = lgr[1] * d1 * inv + lbr[1];
            sm[OFF_PART1 + lkk * 65 + ls * 4 + 2] = lgr[2] * d2 * inv + lbr[2];
            sm[OFF_PART1 + lkk * 65 + ls * 4 + 3] = lgr[3] * d3 * inv + lbr[3];
        }
        __syncthreads();

        // ---------- stage 6: MLP layer 1 (64 -> 128, FFMA2, t_h=8) ----------
        {
            ull hacc[4];
#pragma unroll
            for (int j = 0; j < 4; ++j) hacc[j] = b1p[j];
            const float* pb = sm + OFF_PART1 + k * 65;
            const ulonglong2* w1v = reinterpret_cast<const ulonglong2*>(sm + OFF_W1) + g * 2;
#pragma unroll 4
            for (int p = 0; p < 64; ++p) {
                float xv = pb[p];
                ull xx; PK2(xx, xv);
                ulonglong2 wa = w1v[p * 32];
                ulonglong2 wb = w1v[p * 32 + 1];
                FMA2(hacc[0], xx, wa.x, hacc[0]);
                FMA2(hacc[1], xx, wa.y, hacc[1]);
                FMA2(hacc[2], xx, wb.x, hacc[2]);
                FMA2(hacc[3], xx, wb.y, hacc[3]);
            }
            float* hb = sm + OFF_H + k * 129 + g * 8;
#pragma unroll
            for (int j = 0; j < 4; ++j) {
                float lo, hi;
                UPK2(lo, hi, hacc[j]);
                hb[2 * j + 0] = gelu_f(lo);
                hb[2 * j + 1] = gelu_f(hi);
            }
        }
        __syncthreads();

        // ---------- stage 7: MLP layer 2 (128 -> 64, FFMA2, t_p=4) ----------
        {
            ull o2[2];
            o2[0] = b2p[0]; o2[1] = b2p[1];
            const float* hr = sm + OFF_H + k * 129;
            const ulonglong2* w2v = reinterpret_cast<const ulonglong2*>(sm + OFF_W2) + g;
#pragma unroll 8
            for (int j = 0; j < 128; ++j) {
                float xv = hr[j];
                ull xx; PK2(xx, xv);
                ulonglong2 w = w2v[j * 16];
                FMA2(o2[0], xx, w.x, o2[0]);
                FMA2(o2[1], xx, w.y, o2[1]);
            }
            float4 o;
            UPK2(o.x, o.y, o2[0]);
            UPK2(o.z, o.w, o2[1]);
            reinterpret_cast<float4*>(outPair)[(n * KC + k) * 16 + g] = o;
        }
        // loop-top syncs order region reuse for the next n
    }
}

extern "C" void kernel_launch(void* const* d_in, const int* in_sizes, int n_in,
                              void* d_out, int out_size) {
    const float* pos   = (const float*)d_in[0];
    const float* dmap  = (const float*)d_in[1];
    const int*   nbrs  = (const int*)d_in[2];
    const int*   resi  = (const int*)d_in[3];
    const int*   chain = (const int*)d_in[4];
    const int*   batch = (const int*)d_in[5];
    const float* maskp = (const float*)d_in[6];
    const float* Wrel  = (const float*)d_in[7];
    const float* Wdmap = (const float*)d_in[8];
    const float* Wdist = (const float*)d_in[9];
    const float* Wdir  = (const float*)d_in[10];
    const float* Wrot  = (const float*)d_in[11];
    const float* Wvec  = (const float*)d_in[12];
    const float* lng   = (const float*)d_in[13];
    const float* lnb   = (const float*)d_in[14];
    const float* W1    = (const float*)d_in[15];
    const float* b1    = (const float*)d_in[16];
    const float* W2    = (const float*)d_in[17];
    const float* b2    = (const float*)d_in[18];

    float* outPair = (float*)d_out;
    float* outMask = outPair + (long)Ntot * KC * PC;

    cudaFuncSetAttribute(dsd_kernel, cudaFuncAttributeMaxDynamicSharedMemorySize, SMEMF * 4);
    int sms = 148;
    cudaDeviceGetAttribute(&sms, cudaDevAttrMultiProcessorCount, 0);

    dsd_kernel<<<sms, THREADS, SMEMF * 4>>>(
        pos, dmap, nbrs, resi, chain, batch, maskp,
        Wrel, Wdmap, Wdist, Wdir, Wrot, Wvec, lng, lnb, W1, b1, W2, b2,
        outPair, outMask);
}

// round 6
// speedup vs baseline: 2.5001x; 1.2344x over previous
#include <cuda_runtime.h>
#include <cuda_fp16.h>
#include <math.h>

typedef unsigned long long ull;

#define Ntot 8192
#define KC   32
#define PC   64
#define FEATC 455
#define FSC   457
#define THREADS 512

// ---- shared memory layout (float offsets) ----
#define OFF_WD    0                        // 455*64 = 29120 (fp32 weights)
#define OFF_W1    29120                    // 64*128 = 8192
#define OFF_R     37312                    // reused: features half2[32][457] = 14624 fl  OR  W2(8192)+H(4128)
#define OFF_W2    (OFF_R)                  // 128*64 = 8192
#define OFF_H     (OFF_R + 8192)           // 32*129 = 4128
#define OFF_P0    (OFF_R + 14624)          // 32*66 = 2112 (n0 partials / LN'd pair stride 65)
#define OFF_P1    (OFF_P0 + 2112)          // 32*66 = 2112 (n1)
#define OFF_PJ    (OFF_P1 + 2112)          // [b][32][16] = 1024
#define OFF_POSN  (OFF_PJ + 1024)          // [b][16] = 32
#define OFF_RN    (OFF_POSN + 32)          // [b][12] = 24
#define OFF_SJ    (OFF_RN + 24)            // [b][32] ints = 64
#define OFF_SREL  (OFF_SJ + 64)            // 64
#define OFF_SSAME (OFF_SREL + 64)          // 64
#define OFF_SPM   (OFF_SSAME + 64)         // 64
#define SMEMF     (OFF_SPM + 64)           // 57496 floats = 229984 B (< 232448 limit)

// ---- packed f32x2 helpers ----
#define FMA2(d, a, b, c) asm("fma.rn.f32x2 %0, %1, %2, %3;" : "=l"(d) : "l"(a), "l"(b), "l"(c))
#define ADD2(d, a, b)    asm("add.rn.f32x2 %0, %1, %2;"     : "=l"(d) : "l"(a), "l"(b))
#define PK2(r, x)        asm("mov.b64 %0, {%1, %1};"        : "=l"(r) : "f"(x))
#define PK2D(r, x, y)    asm("mov.b64 %0, {%1, %2};"        : "=l"(r) : "f"(x), "f"(y))
#define UPK2(lo, hi, v)  asm("mov.b64 {%0, %1}, %2;"        : "=f"(lo), "=f"(hi) : "l"(v))

// ---------------- RBF: 16 bins, 3 exps, fp16 output at stride-2 halfs ----------------
__device__ __forceinline__ void rbf16h(float d, __half* out2) {
    const float SI = 0.72727272727f;   // 16/22
    const float G  = 1.06666666667f;   // 16/15
    const float Q  = 0.10273954f;      // exp(-2*G*G)
    float g = d * SI;
    int m = __float2int_rn(g * 0.9375f);
    m = m < 0 ? 0 : (m > 15 ? 15 : m);
    float u = g - (float)m * G;
    float peak = __expf(-u * u);
    float r = __expf(G * (2.0f * u - G));
    float s = __expf(-G * (2.0f * u + G));
    out2[2 * m] = __float2half(peak);
    float v = peak;
#pragma unroll
    for (int st = 1; st <= 15; ++st) {
        v *= r; r *= Q;
        int i = m + st;
        if (i <= 15) out2[2 * i] = __float2half(v);
    }
    v = peak;
#pragma unroll
    for (int st = 1; st <= 15; ++st) {
        v *= s; s *= Q;
        int i = m - st;
        if (i >= 0) out2[2 * i] = __float2half(v);
    }
}

__device__ __forceinline__ void frames_from(const float* p,
                                            float e1[3], float e2[3], float e3[3], float t[3]) {
    t[0] = p[3]; t[1] = p[4]; t[2] = p[5];
    float v1x = p[6] - t[0], v1y = p[7] - t[1], v1z = p[8] - t[2];
    float v2x = p[0] - t[0], v2y = p[1] - t[1], v2z = p[2] - t[2];
    float n1 = sqrtf(v1x * v1x + v1y * v1y + v1z * v1z) + 1e-6f;
    e1[0] = v1x / n1; e1[1] = v1y / n1; e1[2] = v1z / n1;
    float dt = v2x * e1[0] + v2y * e1[1] + v2z * e1[2];
    float ux = v2x - dt * e1[0], uy = v2y - dt * e1[1], uz = v2z - dt * e1[2];
    float n2 = sqrtf(ux * ux + uy * uy + uz * uz) + 1e-6f;
    e2[0] = ux / n2; e2[1] = uy / n2; e2[2] = uz / n2;
    e3[0] = e1[1] * e2[2] - e1[2] * e2[1];
    e3[1] = e1[2] * e2[0] - e1[0] * e2[2];
    e3[2] = e1[0] * e2[1] - e1[1] * e2[0];
}

__device__ __forceinline__ float gelu_f(float x) {
    float c = 0.7978845608028654f * (x + 0.044715f * x * x * x);
    float t;
    asm("tanh.approx.f32 %0, %1;" : "=f"(t) : "f"(c));
    return 0.5f * x * (1.0f + t);
}

__global__ void __launch_bounds__(THREADS, 1)
dsd_kernel(const float* __restrict__ pos, const float* __restrict__ dmap,
           const int* __restrict__ nbrs, const int* __restrict__ resi,
           const int* __restrict__ chain, const int* __restrict__ batch,
           const float* __restrict__ maskp,
           const float* __restrict__ Wrel, const float* __restrict__ Wdmap,
           const float* __restrict__ Wdist, const float* __restrict__ Wdir,
           const float* __restrict__ Wrot, const float* __restrict__ Wvec,
           const float* __restrict__ lng, const float* __restrict__ lnb,
           const float* __restrict__ W1, const float* __restrict__ b1,
           const float* __restrict__ W2, const float* __restrict__ b2,
           float* __restrict__ outPair, float* __restrict__ outMask)
{
    extern __shared__ float sm[];
    const int tid = threadIdx.x;
    const int k   = tid & 31;         // lane = neighbor slot
    const int wid = tid >> 5;         // warp id (0..15)
    const int pg  = wid & 7;          // p-group (8 cols each)
    const int fh  = wid >> 3;         // feature half (0..1)
    const int lkk = tid >> 4;         // LN: k
    const int ls  = tid & 15;         // LN: col quad
    const int g   = wid;              // MLP group

    // ---- stage constant weights once ----
    for (int i = tid; i < 400 * 64; i += THREADS) sm[OFF_WD + i] = Wdist[i];
    for (int i = tid; i < 16 * 64; i += THREADS) sm[OFF_WD + 400 * 64 + i] = Wdmap[i];
    for (int i = tid; i < 15 * 64; i += THREADS) sm[OFF_WD + 416 * 64 + i] = Wdir[i];
    for (int i = tid; i < 15 * 64; i += THREADS) sm[OFF_WD + 431 * 64 + i] = Wvec[i];
    for (int i = tid; i < 9 * 64; i += THREADS) sm[OFF_WD + 446 * 64 + i] = Wrot[i];
    for (int i = tid; i < 64 * 128; i += THREADS) sm[OFF_W1 + i] = W1[i];

    float lgr[4], lbr[4];
    ull b1p[4], b2p[2];
#pragma unroll
    for (int i = 0; i < 4; ++i) {
        lgr[i] = lng[ls * 4 + i];
        lbr[i] = lnb[ls * 4 + i];
    }
#pragma unroll
    for (int i = 0; i < 4; ++i) { float a = b1[g * 8 + 2 * i], b = b1[g * 8 + 2 * i + 1]; PK2D(b1p[i], a, b); }
#pragma unroll
    for (int i = 0; i < 2; ++i) { float a = b2[g * 4 + 2 * i], b = b2[g * 4 + 2 * i + 1]; PK2D(b2p[i], a, b); }

    const int fbeg = fh ? 228 : 0;
    const int fend = fh ? 455 : 228;

    __syncthreads();

    int* smi = (int*)sm;
    __half* F = (__half*)(sm + OFF_R);

    for (int n0 = blockIdx.x * 2; n0 < Ntot; n0 += gridDim.x * 2) {
        // ---------- stage 1: meta + frames + pos for both n ----------
        if (tid < 64) {
            int b = tid >> 5, kk = tid & 31;
            int n = n0 + b;
            int nb = nbrs[n * KC + kk];
            int j = nb < 0 ? 0 : nb;
            float valid = (nb != -1) ? 1.0f : 0.0f;
            smi[OFF_SJ + b * 32 + kk] = j;
            int dr = resi[j] - resi[n];
            dr = dr < -32 ? -32 : (dr > 32 ? 32 : dr);
            smi[OFF_SREL + b * 32 + kk] = dr + 32;
            float same = (chain[j] == chain[n] && batch[j] == batch[n]) ? 1.0f : 0.0f;
            sm[OFF_SSAME + b * 32 + kk] = same;
            float pm = maskp[n] * maskp[j] * valid;
            sm[OFF_SPM + b * 32 + kk] = pm;
            outMask[n * KC + kk] = pm;
        } else if (tid < 66) {
            int b = tid - 64;
            float e1[3], e2[3], e3[3], t[3], prow[9];
#pragma unroll
            for (int i = 0; i < 9; ++i) prow[i] = pos[(n0 + b) * 15 + i];
            frames_from(prow, e1, e2, e3, t);
#pragma unroll
            for (int r = 0; r < 3; ++r) {
                sm[OFF_RN + b * 12 + r * 3 + 0] = e1[r];
                sm[OFF_RN + b * 12 + r * 3 + 1] = e2[r];
                sm[OFF_RN + b * 12 + r * 3 + 2] = e3[r];
            }
            sm[OFF_RN + b * 12 + 9 + 0] = t[0];
            sm[OFF_RN + b * 12 + 9 + 1] = t[1];
            sm[OFF_RN + b * 12 + 9 + 2] = t[2];
        } else if (tid >= 96 && tid < 126) {
            int b = (tid - 96) / 15, e = (tid - 96) % 15;
            sm[OFF_POSN + b * 16 + e] = pos[(n0 + b) * 15 + e];
        }
        __syncthreads();

        // ---------- stage 2: gather neighbor positions (both n) ----------
        for (int i = tid; i < 960; i += THREADS) {
            int b = i / 480, r2 = i - b * 480;
            int kk = r2 / 15, e = r2 - kk * 15;
            int j = smi[OFF_SJ + b * 32 + kk];
            sm[OFF_PJ + b * 512 + kk * 16 + e] = pos[j * 15 + e];
        }
        __syncthreads();

        // ---------- stage 3: build features (fp16, interleaved by b) ----------
        for (int b = 0; b < 2; ++b) {
            __half* fk = F + (k * FSC) * 2 + b;   // element f at fk[2*f]
            const float* pn = sm + OFF_POSN + b * 16;
            const float* pj = sm + OFF_PJ + b * 512 + k * 16;
            const float* rn = sm + OFF_RN + b * 12;
            {   // distance pair dp = wid (0..15)
                int a = wid / 5, bb = wid - a * 5;
                float dx = pn[a * 3 + 0] - pj[bb * 3 + 0];
                float dy = pn[a * 3 + 1] - pj[bb * 3 + 1];
                float dz = pn[a * 3 + 2] - pj[bb * 3 + 2];
                float d = sqrtf(dx * dx + dy * dy + dz * dz);
                rbf16h(d, fk + wid * 32);
            }
            if (wid < 9) {   // dp = 16 + wid
                int dp = 16 + wid;
                int a = dp / 5, bb = dp - a * 5;
                float dx = pn[a * 3 + 0] - pj[bb * 3 + 0];
                float dy = pn[a * 3 + 1] - pj[bb * 3 + 1];
                float dz = pn[a * 3 + 2] - pj[bb * 3 + 2];
                float d = sqrtf(dx * dx + dy * dy + dz * dz);
                rbf16h(d, fk + dp * 32);
            } else if (wid == 9) {   // dmap rbf, masked
                int j = smi[OFF_SJ + b * 32 + k];
                float pm = sm[OFF_SPM + b * 32 + k];
                float dval = __ldg(&dmap[(long)(n0 + b) * Ntot + j]);
                if (pm > 0.0f) {
                    rbf16h(dval, fk + 400 * 2);
                } else {
                    __half z = __float2half(0.0f);
#pragma unroll
                    for (int i = 0; i < 16; ++i) fk[(400 + i) * 2] = z;
                }
            } else if (wid < 15) {   // rel_vec + dirs, atom a = wid-10
                int a = wid - 10;
                float v0 = pj[a * 3 + 0] - rn[9 + 0];
                float v1 = pj[a * 3 + 1] - rn[9 + 1];
                float v2 = pj[a * 3 + 2] - rn[9 + 2];
                float rv[3];
#pragma unroll
                for (int i = 0; i < 3; ++i)
                    rv[i] = rn[0 + i] * v0 + rn[3 + i] * v1 + rn[6 + i] * v2;
                float nr = sqrtf(rv[0] * rv[0] + rv[1] * rv[1] + rv[2] * rv[2]);
                float inv = 1.0f / (nr + 1e-6f);
#pragma unroll
                for (int i = 0; i < 3; ++i) {
                    fk[(416 + a * 3 + i) * 2] = __float2half(rv[i] * inv);
                    fk[(431 + a * 3 + i) * 2] = __float2half(rv[i] * 0.1f);
                }
            } else {   // wid == 15: rotation features
                float e1j[3], e2j[3], e3j[3], tj[3];
                frames_from(pj, e1j, e2j, e3j, tj);
#pragma unroll
                for (int i = 0; i < 3; ++i) {
                    float r0 = rn[0 + i], r1 = rn[3 + i], r2 = rn[6 + i];
                    fk[(446 + i * 3 + 0) * 2] = __float2half(r0 * e1j[0] + r1 * e1j[1] + r2 * e1j[2]);
                    fk[(446 + i * 3 + 1) * 2] = __float2half(r0 * e2j[0] + r1 * e2j[1] + r2 * e2j[2]);
                    fk[(446 + i * 3 + 2) * 2] = __float2half(r0 * e3j[0] + r1 * e3j[1] + r2 * e3j[2]);
                }
            }
        }
        __syncthreads();

        // ---------- stage 4: projection for BOTH n, 8 p-groups x 2 f-halves ----------
        ull acc[8];   // [0..3] n0 cols pg*8..+7, [4..7] n1
#pragma unroll
        for (int j = 0; j < 8; ++j) acc[j] = 0ull;
        {
            const __half2* xh = (const __half2*)(sm + OFF_R) + k * FSC;
            const ulonglong2* w = reinterpret_cast<const ulonglong2*>(sm + OFF_WD) + pg * 2;
#pragma unroll 2
            for (int f = fbeg; f < fend; ++f) {
                float2 x2 = __half22float2(xh[f]);
                ull xa, xb;
                PK2(xa, x2.x);
                PK2(xb, x2.y);
                ulonglong2 u0 = w[f * 16];
                ulonglong2 u1 = w[f * 16 + 1];
                FMA2(acc[0], xa, u0.x, acc[0]); FMA2(acc[1], xa, u0.y, acc[1]);
                FMA2(acc[2], xa, u1.x, acc[2]); FMA2(acc[3], xa, u1.y, acc[3]);
                FMA2(acc[4], xb, u0.x, acc[4]); FMA2(acc[5], xb, u0.y, acc[5]);
                FMA2(acc[6], xb, u1.x, acc[6]); FMA2(acc[7], xb, u1.y, acc[7]);
            }
        }
        if (fh == 0) {
            ull* p0 = (ull*)(sm + OFF_P0) + k * 33 + pg * 4;
            ull* p1 = (ull*)(sm + OFF_P1) + k * 33 + pg * 4;
#pragma unroll
            for (int j = 0; j < 4; ++j) { p0[j] = acc[j]; p1[j] = acc[4 + j]; }
        }
        __syncthreads();   // all feature reads done; fh0 stores visible
        if (fh == 1) {
            ull* p0 = (ull*)(sm + OFF_P0) + k * 33 + pg * 4;
            ull* p1 = (ull*)(sm + OFF_P1) + k * 33 + pg * 4;
#pragma unroll
            for (int j = 0; j < 4; ++j) {
                ull t0 = p0[j]; ADD2(t0, t0, acc[j]);     p0[j] = t0;
                ull t1 = p1[j]; ADD2(t1, t1, acc[4 + j]); p1[j] = t1;
            }
        }
        // restage W2 into the (now dead) feature region
        for (int i = tid; i < 128 * 64; i += THREADS) sm[OFF_W2 + i] = W2[i];
        __syncthreads();

        // ---------- stage 5: + Wrel, LayerNorm for both n ----------
        {
            float a0 = sm[OFF_P0 + lkk * 66 + ls * 4 + 0];
            float a1 = sm[OFF_P0 + lkk * 66 + ls * 4 + 1];
            float a2 = sm[OFF_P0 + lkk * 66 + ls * 4 + 2];
            float a3 = sm[OFF_P0 + lkk * 66 + ls * 4 + 3];
            float c0 = sm[OFF_P1 + lkk * 66 + ls * 4 + 0];
            float c1 = sm[OFF_P1 + lkk * 66 + ls * 4 + 1];
            float c2 = sm[OFF_P1 + lkk * 66 + ls * 4 + 2];
            float c3 = sm[OFF_P1 + lkk * 66 + ls * 4 + 3];
            {
                int rel = smi[OFF_SREL + lkk];
                float same = sm[OFF_SSAME + lkk];
                float4 wr = __ldg(reinterpret_cast<const float4*>(Wrel) + rel * 16 + ls);
                a0 = fmaf(same, wr.x, a0); a1 = fmaf(same, wr.y, a1);
                a2 = fmaf(same, wr.z, a2); a3 = fmaf(same, wr.w, a3);
            }
            {
                int rel = smi[OFF_SREL + 32 + lkk];
                float same = sm[OFF_SSAME + 32 + lkk];
                float4 wr = __ldg(reinterpret_cast<const float4*>(Wrel) + rel * 16 + ls);
                c0 = fmaf(same, wr.x, c0); c1 = fmaf(same, wr.y, c1);
                c2 = fmaf(same, wr.z, c2); c3 = fmaf(same, wr.w, c3);
            }
            __syncthreads();   // reads done before stride-65 overwrite

            // LN n0
            {
                float ssum = a0 + a1 + a2 + a3;
                ssum += __shfl_xor_sync(0xffffffffu, ssum, 8);
                ssum += __shfl_xor_sync(0xffffffffu, ssum, 4);
                ssum += __shfl_xor_sync(0xffffffffu, ssum, 2);
                ssum += __shfl_xor_sync(0xffffffffu, ssum, 1);
                float mu = ssum * 0.015625f;
                float d0 = a0 - mu, d1 = a1 - mu, d2 = a2 - mu, d3 = a3 - mu;
                float sq = d0 * d0 + d1 * d1 + d2 * d2 + d3 * d3;
                sq += __shfl_xor_sync(0xffffffffu, sq, 8);
                sq += __shfl_xor_sync(0xffffffffu, sq, 4);
                sq += __shfl_xor_sync(0xffffffffu, sq, 2);
                sq += __shfl_xor_sync(0xffffffffu, sq, 1);
                float inv = rsqrtf(sq * 0.015625f + 1e-5f);
                sm[OFF_P0 + lkk * 65 + ls * 4 + 0] = lgr[0] * d0 * inv + lbr[0];
                sm[OFF_P0 + lkk * 65 + ls * 4 + 1] = lgr[1] * d1 * inv + lbr[1];
                sm[OFF_P0 + lkk * 65 + ls * 4 + 2] = lgr[2] * d2 * inv + lbr[2];
                sm[OFF_P0 + lkk * 65 + ls * 4 + 3] = lgr[3] * d3 * inv + lbr[3];
            }
            // LN n1
            {
                float ssum = c0 + c1 + c2 + c3;
                ssum += __shfl_xor_sync(0xffffffffu, ssum, 8);
                ssum += __shfl_xor_sync(0xffffffffu, ssum, 4);
                ssum += __shfl_xor_sync(0xffffffffu, ssum, 2);
                ssum += __shfl_xor_sync(0xffffffffu, ssum, 1);
                float mu = ssum * 0.015625f;
                float d0 = c0 - mu, d1 = c1 - mu, d2 = c2 - mu, d3 = c3 - mu;
                float sq = d0 * d0 + d1 * d1 + d2 * d2 + d3 * d3;
                sq += __shfl_xor_sync(0xffffffffu, sq, 8);
                sq += __shfl_xor_sync(0xffffffffu, sq, 4);
                sq += __shfl_xor_sync(0xffffffffu, sq, 2);
                sq += __shfl_xor_sync(0xffffffffu, sq, 1);
                float inv = rsqrtf(sq * 0.015625f + 1e-5f);
                sm[OFF_P1 + lkk * 65 + ls * 4 + 0] = lgr[0] * d0 * inv + lbr[0];
                sm[OFF_P1 + lkk * 65 + ls * 4 + 1] = lgr[1] * d1 * inv + lbr[1];
                sm[OFF_P1 + lkk * 65 + ls * 4 + 2] = lgr[2] * d2 * inv + lbr[2];
                sm[OFF_P1 + lkk * 65 + ls * 4 + 3] = lgr[3] * d3 * inv + lbr[3];
            }
        }
        __syncthreads();

        // ---------- stages 6-7: MLP for each n ----------
#pragma unroll 1
        for (int b = 0; b < 2; ++b) {
            const int pairOff = b ? OFF_P1 : OFF_P0;
            // MLP layer 1: 64 -> 128
            {
                ull hacc[4];
#pragma unroll
                for (int j = 0; j < 4; ++j) hacc[j] = b1p[j];
                const float* pb = sm + pairOff + k * 65;
                const ulonglong2* w1v = reinterpret_cast<const ulonglong2*>(sm + OFF_W1) + g * 2;
#pragma unroll 4
                for (int p = 0; p < 64; ++p) {
                    float xv = pb[p];
                    ull xx; PK2(xx, xv);
                    ulonglong2 wa = w1v[p * 32];
                    ulonglong2 wb = w1v[p * 32 + 1];
                    FMA2(hacc[0], xx, wa.x, hacc[0]);
                    FMA2(hacc[1], xx, wa.y, hacc[1]);
                    FMA2(hacc[2], xx, wb.x, hacc[2]);
                    FMA2(hacc[3], xx, wb.y, hacc[3]);
                }
                float* hb = sm + OFF_H + k * 129 + g * 8;
#pragma unroll
                for (int j = 0; j < 4; ++j) {
                    float lo, hi;
                    UPK2(lo, hi, hacc[j]);
                    hb[2 * j + 0] = gelu_f(lo);
                    hb[2 * j + 1] = gelu_f(hi);
                }
            }
            __syncthreads();
            // MLP layer 2: 128 -> 64
            {
                ull o2[2];
                o2[0] = b2p[0]; o2[1] = b2p[1];
                const float* hr = sm + OFF_H + k * 129;
                const ulonglong2* w2v = reinterpret_cast<const ulonglong2*>(sm + OFF_W2) + g;
#pragma unroll 8
                for (int j = 0; j < 128; ++j) {
                    float xv = hr[j];
                    ull xx; PK2(xx, xv);
                    ulonglong2 w = w2v[j * 16];
                    FMA2(o2[0], xx, w.x, o2[0]);
                    FMA2(o2[1], xx, w.y, o2[1]);
                }
                float4 o;
                UPK2(o.x, o.y, o2[0]);
                UPK2(o.z, o.w, o2[1]);
                reinterpret_cast<float4*>(outPair)[((n0 + b) * KC + k) * 16 + g] = o;
            }
            __syncthreads();
        }
        // loop-top stage-1 follows the final barrier
    }
}

extern "C" void kernel_launch(void* const* d_in, const int* in_sizes, int n_in,
                              void* d_out, int out_size) {
    const float* pos   = (const float*)d_in[0];
    const float* dmap  = (const float*)d_in[1];
    const int*   nbrs  = (const int*)d_in[2];
    const int*   resi  = (const int*)d_in[3];
    const int*   chain = (const int*)d_in[4];
    const int*   batch = (const int*)d_in[5];
    const float* maskp = (const float*)d_in[6];
    const float* Wrel  = (const float*)d_in[7];
    const float* Wdmap = (const float*)d_in[8];
    const float* Wdist = (const float*)d_in[9];
    const float* Wdir  = (const float*)d_in[10];
    const float* Wrot  = (const float*)d_in[11];
    const float* Wvec  = (const float*)d_in[12];
    const float* lng   = (const float*)d_in[13];
    const float* lnb   = (const float*)d_in[14];
    const float* W1    = (const float*)d_in[15];
    const float* b1    = (const float*)d_in[16];
    const float* W2    = (const float*)d_in[17];
    const float* b2    = (const float*)d_in[18];

    float* outPair = (float*)d_out;
    float* outMask = outPair + (long)Ntot * KC * PC;

    cudaFuncSetAttribute(dsd_kernel, cudaFuncAttributeMaxDynamicSharedMemorySize, SMEMF * 4);
    int sms = 148;
    cudaDeviceGetAttribute(&sms, cudaDevAttrMultiProcessorCount, 0);

    dsd_kernel<<<sms, THREADS, SMEMF * 4>>>(
        pos, dmap, nbrs, resi, chain, batch, maskp,
        Wrel, Wdmap, Wdist, Wdir, Wrot, Wvec, lng, lnb, W1, b1, W2, b2,
        outPair, outMask);
}